// round 1
// baseline (speedup 1.0000x reference)
#include <cuda_runtime.h>
#include <cuda_bf16.h>

// Problem constants
#define DIMC    192
#define QKV_N   576
#define NWIN    144          // tokens per window
#define NHEADS  6
#define HD      32
#define TOW     64           // number of window types == nW
#define BATCH   30
#define MTOT    (BATCH * TOW * NWIN)   // 276480 rows
#define ATT_SCALE 0.17677669529663687f // 32^-0.5

// Scratch (static device arrays; allocation-free per harness rules)
static __device__ float g_qkv[(size_t)MTOT * QKV_N];        // 637 MB
static __device__ float g_att[(size_t)MTOT * DIMC];         // 212 MB
static __device__ float g_biasg[(size_t)NHEADS * TOW * NWIN * NWIN]; // 32 MB

// ---------------------------------------------------------------------------
// GEMM: C[M,N] = A[M,K] @ B[N,K]^T + bias[N]; cols < scaleCols scaled by scale.
// BM=256, BN=64, BK=8, 256 threads, 8x8 per-thread micro-tile.
// Requires M % 256 == 0, N % 64 == 0, K % 8 == 0.
// ---------------------------------------------------------------------------
__global__ __launch_bounds__(256, 2)
void gemm_bias_kernel(const float* __restrict__ A, const float* __restrict__ B,
                      const float* __restrict__ bias, float* __restrict__ C,
                      int N, int K, int scaleCols, float scale)
{
    __shared__ float As[8 * 256];   // As[k][m]
    __shared__ float Bs[8 * 64];    // Bs[k][n]

    const int tid = threadIdx.x;
    const int m0  = blockIdx.y * 256;
    const int n0  = blockIdx.x * 64;
    const int tx  = tid & 7;    // 8 n-groups of 8
    const int ty  = tid >> 3;   // 32 m-groups of 8

    float acc[8][8];
#pragma unroll
    for (int r = 0; r < 8; r++)
#pragma unroll
        for (int s = 0; s < 8; s++) acc[r][s] = 0.f;

    const size_t arow = (size_t)(m0 + tid) * K;

    for (int k0 = 0; k0 < K; k0 += 8) {
        // stage loads in registers
        float4 a0 = *(const float4*)&A[arow + k0];
        float4 a1 = *(const float4*)&A[arow + k0 + 4];
        float4 bb = make_float4(0.f, 0.f, 0.f, 0.f);
        int bn = 0, bk = 0;
        if (tid < 128) {
            bn = tid >> 1;
            bk = (tid & 1) * 4;
            bb = *(const float4*)&B[(size_t)(n0 + bn) * K + k0 + bk];
        }
        __syncthreads();   // previous iteration's compute done
        As[0 * 256 + tid] = a0.x; As[1 * 256 + tid] = a0.y;
        As[2 * 256 + tid] = a0.z; As[3 * 256 + tid] = a0.w;
        As[4 * 256 + tid] = a1.x; As[5 * 256 + tid] = a1.y;
        As[6 * 256 + tid] = a1.z; As[7 * 256 + tid] = a1.w;
        if (tid < 128) {
            Bs[(bk + 0) * 64 + bn] = bb.x;
            Bs[(bk + 1) * 64 + bn] = bb.y;
            Bs[(bk + 2) * 64 + bn] = bb.z;
            Bs[(bk + 3) * 64 + bn] = bb.w;
        }
        __syncthreads();

#pragma unroll
        for (int k = 0; k < 8; k++) {
            float4 av0 = *(const float4*)&As[k * 256 + ty * 8];
            float4 av1 = *(const float4*)&As[k * 256 + ty * 8 + 4];
            float4 bv0 = *(const float4*)&Bs[k * 64 + tx * 8];
            float4 bv1 = *(const float4*)&Bs[k * 64 + tx * 8 + 4];
            float a[8] = {av0.x, av0.y, av0.z, av0.w, av1.x, av1.y, av1.z, av1.w};
            float b[8] = {bv0.x, bv0.y, bv0.z, bv0.w, bv1.x, bv1.y, bv1.z, bv1.w};
#pragma unroll
            for (int r = 0; r < 8; r++)
#pragma unroll
                for (int s = 0; s < 8; s++)
                    acc[r][s] = fmaf(a[r], b[s], acc[r][s]);
        }
    }

    // epilogue: +bias, optional scale, vectorized stores
    float bcol[8];
#pragma unroll
    for (int s = 0; s < 8; s++) bcol[s] = bias[n0 + tx * 8 + s];
#pragma unroll
    for (int r = 0; r < 8; r++) {
        size_t row = (size_t)(m0 + ty * 8 + r);
        float v[8];
#pragma unroll
        for (int s = 0; s < 8; s++) {
            int col = n0 + tx * 8 + s;
            float t = acc[r][s] + bcol[s];
            if (col < scaleCols) t *= scale;
            v[s] = t;
        }
        *(float4*)&C[row * N + n0 + tx * 8 + 0] = make_float4(v[0], v[1], v[2], v[3]);
        *(float4*)&C[row * N + n0 + tx * 8 + 4] = make_float4(v[4], v[5], v[6], v[7]);
    }
}

// ---------------------------------------------------------------------------
// Pre-gather earth position bias into linear [H][W][144][144]
// ---------------------------------------------------------------------------
__global__ void bias_gather_kernel(const float* __restrict__ table,
                                   const int* __restrict__ pos)
{
    const int w = blockIdx.x, h = blockIdx.y;
    float* dst = g_biasg + (size_t)(h * TOW + w) * (NWIN * NWIN);
    for (int idx = threadIdx.x; idx < NWIN * NWIN; idx += blockDim.x) {
        int p = pos[idx];
        dst[idx] = table[((size_t)p * TOW + w) * NHEADS + h];
    }
}

// ---------------------------------------------------------------------------
// Attention: one CTA per (b, w, h).
// smem: Qt[32][144], Kt[32][144], Vs[144][32], S[144][145] (pitch 145)
// ---------------------------------------------------------------------------
#define S_PITCH 145
#define ATTN_SMEM ((2 * 32 * 144 + 144 * 32 + 144 * S_PITCH) * 4)

__global__ __launch_bounds__(256)
void attn_kernel()
{
    extern __shared__ float sm[];
    float* Qt = sm;                    // [32][144]  (transposed)
    float* Kt = Qt + 32 * 144;         // [32][144]
    float* Vs = Kt + 32 * 144;         // [144][32]
    float* S  = Vs + 144 * 32;         // [144][S_PITCH]

    const int w = blockIdx.x, b = blockIdx.y, h = blockIdx.z;
    const int tid = threadIdx.x;

    const size_t base = (size_t)(b * TOW + w) * NWIN * QKV_N + h * HD;

    // load Q^T, K^T, V (q already scaled by GEMM epilogue)
    for (int idx = tid; idx < NWIN * 8; idx += 256) {
        int i = idx >> 3;
        int e0 = (idx & 7) * 4;
        const float* p = &g_qkv[base + (size_t)i * QKV_N + e0];
        float4 q  = *(const float4*)(p);
        float4 kk = *(const float4*)(p + 192);
        float4 vv = *(const float4*)(p + 384);
        Qt[(e0 + 0) * 144 + i] = q.x;  Qt[(e0 + 1) * 144 + i] = q.y;
        Qt[(e0 + 2) * 144 + i] = q.z;  Qt[(e0 + 3) * 144 + i] = q.w;
        Kt[(e0 + 0) * 144 + i] = kk.x; Kt[(e0 + 1) * 144 + i] = kk.y;
        Kt[(e0 + 2) * 144 + i] = kk.z; Kt[(e0 + 3) * 144 + i] = kk.w;
        *(float4*)&Vs[i * 32 + e0] = vv;
    }
    __syncthreads();

    // S = Q K^T + bias   (4x4 micro-tiles)
    const float* bptr = g_biasg + (size_t)(h * TOW + w) * (NWIN * NWIN);
    for (int t = tid; t < 36 * 36; t += 256) {
        int i0 = (t / 36) * 4;
        int j0 = (t % 36) * 4;
        float acc[4][4];
#pragma unroll
        for (int r = 0; r < 4; r++)
#pragma unroll
            for (int s = 0; s < 4; s++) acc[r][s] = 0.f;
#pragma unroll
        for (int e = 0; e < 32; e++) {
            float4 qa = *(const float4*)&Qt[e * 144 + i0];
            float4 kb = *(const float4*)&Kt[e * 144 + j0];
            float qr[4] = {qa.x, qa.y, qa.z, qa.w};
            float kс[4] = {kb.x, kb.y, kb.z, kb.w};
#pragma unroll
            for (int r = 0; r < 4; r++)
#pragma unroll
                for (int s = 0; s < 4; s++)
                    acc[r][s] = fmaf(qr[r], kс[s], acc[r][s]);
        }
#pragma unroll
        for (int r = 0; r < 4; r++) {
            float4 bv = *(const float4*)&bptr[(i0 + r) * 144 + j0];
            S[(i0 + r) * S_PITCH + j0 + 0] = acc[r][0] + bv.x;
            S[(i0 + r) * S_PITCH + j0 + 1] = acc[r][1] + bv.y;
            S[(i0 + r) * S_PITCH + j0 + 2] = acc[r][2] + bv.z;
            S[(i0 + r) * S_PITCH + j0 + 3] = acc[r][3] + bv.w;
        }
    }
    __syncthreads();

    // softmax: one warp per row
    const int warp = tid >> 5, lane = tid & 31;
    for (int r = warp; r < NWIN; r += 8) {
        float* row = &S[r * S_PITCH];
        float mx = -1e30f;
        for (int j = lane; j < NWIN; j += 32) mx = fmaxf(mx, row[j]);
#pragma unroll
        for (int o = 16; o; o >>= 1) mx = fmaxf(mx, __shfl_xor_sync(0xffffffffu, mx, o));
        float sum = 0.f;
        for (int j = lane; j < NWIN; j += 32) {
            float p = __expf(row[j] - mx);
            row[j] = p;
            sum += p;
        }
#pragma unroll
        for (int o = 16; o; o >>= 1) sum += __shfl_xor_sync(0xffffffffu, sum, o);
        float inv = 1.f / sum;
        for (int j = lane; j < NWIN; j += 32) row[j] *= inv;
    }
    __syncthreads();

    // O = P V   (4x4 micro-tiles over (i, e)), write into [b,w,n, h*32+e]
    const size_t obase = (size_t)(b * TOW + w) * NWIN * DIMC + h * HD;
    for (int t = tid; t < 36 * 8; t += 256) {
        int i0 = (t >> 3) * 4;
        int e0 = (t & 7) * 4;
        float acc[4][4];
#pragma unroll
        for (int r = 0; r < 4; r++)
#pragma unroll
            for (int s = 0; s < 4; s++) acc[r][s] = 0.f;
#pragma unroll 4
        for (int j = 0; j < NWIN; j++) {
            float4 vv = *(const float4*)&Vs[j * 32 + e0];
            float p0 = S[(i0 + 0) * S_PITCH + j];
            float p1 = S[(i0 + 1) * S_PITCH + j];
            float p2 = S[(i0 + 2) * S_PITCH + j];
            float p3 = S[(i0 + 3) * S_PITCH + j];
            acc[0][0] = fmaf(p0, vv.x, acc[0][0]); acc[0][1] = fmaf(p0, vv.y, acc[0][1]);
            acc[0][2] = fmaf(p0, vv.z, acc[0][2]); acc[0][3] = fmaf(p0, vv.w, acc[0][3]);
            acc[1][0] = fmaf(p1, vv.x, acc[1][0]); acc[1][1] = fmaf(p1, vv.y, acc[1][1]);
            acc[1][2] = fmaf(p1, vv.z, acc[1][2]); acc[1][3] = fmaf(p1, vv.w, acc[1][3]);
            acc[2][0] = fmaf(p2, vv.x, acc[2][0]); acc[2][1] = fmaf(p2, vv.y, acc[2][1]);
            acc[2][2] = fmaf(p2, vv.z, acc[2][2]); acc[2][3] = fmaf(p2, vv.w, acc[2][3]);
            acc[3][0] = fmaf(p3, vv.x, acc[3][0]); acc[3][1] = fmaf(p3, vv.y, acc[3][1]);
            acc[3][2] = fmaf(p3, vv.z, acc[3][2]); acc[3][3] = fmaf(p3, vv.w, acc[3][3]);
        }
#pragma unroll
        for (int r = 0; r < 4; r++) {
            *(float4*)&g_att[obase + (size_t)(i0 + r) * DIMC + e0] =
                make_float4(acc[r][0], acc[r][1], acc[r][2], acc[r][3]);
        }
    }
}

// ---------------------------------------------------------------------------
extern "C" void kernel_launch(void* const* d_in, const int* in_sizes, int n_in,
                              void* d_out, int out_size)
{
    const float* x      = (const float*)d_in[0];
    const float* qkv_w  = (const float*)d_in[1];
    const float* qkv_b  = (const float*)d_in[2];
    const float* proj_w = (const float*)d_in[3];
    const float* proj_b = (const float*)d_in[4];
    const float* table  = (const float*)d_in[5];
    const int*   pos    = (const int*)d_in[6];
    float* out = (float*)d_out;

    float *qkv_s, *att_s;
    cudaGetSymbolAddress((void**)&qkv_s, g_qkv);
    cudaGetSymbolAddress((void**)&att_s, g_att);

    cudaFuncSetAttribute(attn_kernel, cudaFuncAttributeMaxDynamicSharedMemorySize,
                         ATTN_SMEM);

    // 1) fused QKV projection (+bias, q scaled)
    {
        dim3 grid(QKV_N / 64, MTOT / 256);
        gemm_bias_kernel<<<grid, 256>>>(x, qkv_w, qkv_b, qkv_s,
                                        QKV_N, DIMC, DIMC, ATT_SCALE);
    }
    // 2) bias pre-gather
    {
        dim3 grid(TOW, NHEADS);
        bias_gather_kernel<<<grid, 256>>>(table, pos);
    }
    // 3) windowed attention
    {
        dim3 grid(TOW, BATCH, NHEADS);
        attn_kernel<<<grid, 256, ATTN_SMEM>>>();
    }
    // 4) output projection
    {
        dim3 grid(DIMC / 64, MTOT / 256);
        gemm_bias_kernel<<<grid, 256>>>(att_s, proj_w, proj_b, out,
                                        DIMC, DIMC, 0, 1.0f);
    }
}